// round 15
// baseline (speedup 1.0000x reference)
#include <cuda_runtime.h>
#include <cstdint>

// out[n,o,h,w] = alpha[n]*m[o] * sum_{c,kh,kw} sign(x)*sign(w)
// Hybrid: samples n<NT_ via int8 mma.sync implicit GEMM (tensor pipe),
//         samples n>=NT_ via XNOR+CSA popcount (alu pipe), fused in one grid.

#define N_ 32
#define C_ 256
#define H_ 56
#define W_ 56
#define O_ 256
#define HW_ 3136
#define K_ 2304
#define HP_ 58
#define PT_ 98                  // 3136/32 pixel tiles (exact, N32 CTA tile)
#define NT_ 10                  // samples on tensor path
#define TCTA_ (NT_*PT_*2)       // 1960 tensor CTAs
#define PCTA_ ((N_-NT_)*H_*4)   // 4928 popc CTAs

__device__ __align__(16) int8_t   g_x8[(size_t)N_ * HP_ * HP_ * C_];   // NHWC padded s8 signs
__device__ __align__(16) int8_t   g_w8[(size_t)O_ * K_];               // A rows, k=tap*256+c
__device__ __align__(16) unsigned g_xpack[(size_t)N_ * H_ * W_ * 8];   // [n][h][w][j]
__device__ __align__(16) unsigned g_wpack[O_ * 72];                    // [o][t][j]
__device__ float g_partial[N_ * H_];
__device__ float g_m[O_];

__device__ __forceinline__ uint32_t smem_u32(const void* p) {
    uint32_t a;
    asm("{ .reg .u64 t; cvta.to.shared.u64 t, %1; cvt.u32.u64 %0, t; }" : "=r"(a) : "l"(p));
    return a;
}
__device__ __forceinline__ void cp16(uint32_t saddr, const void* g) {
    asm volatile("cp.async.cg.shared.global [%0], [%1], 16;" :: "r"(saddr), "l"(g));
}
__device__ __forceinline__ void ldsm4(uint32_t* r, uint32_t a) {
    asm volatile("ldmatrix.sync.aligned.m8n8.x4.shared.b16 {%0,%1,%2,%3}, [%4];"
                 : "=r"(r[0]), "=r"(r[1]), "=r"(r[2]), "=r"(r[3]) : "r"(a));
}
__device__ __forceinline__ void ldsm2(uint32_t* r, uint32_t a) {
    asm volatile("ldmatrix.sync.aligned.m8n8.x2.shared.b16 {%0,%1}, [%2];"
                 : "=r"(r[0]), "=r"(r[1]) : "r"(a));
}
__device__ __forceinline__ void mma_s8(int* d, const uint32_t* a, const uint32_t* b) {
    asm volatile("mma.sync.aligned.m16n8k32.row.col.s32.s8.s8.s32 "
                 "{%0,%1,%2,%3}, {%4,%5,%6,%7}, {%8,%9}, {%0,%1,%2,%3};"
                 : "+r"(d[0]), "+r"(d[1]), "+r"(d[2]), "+r"(d[3])
                 : "r"(a[0]), "r"(a[1]), "r"(a[2]), "r"(a[3]), "r"(b[0]), "r"(b[1]));
}
__device__ __forceinline__ void fa(unsigned a, unsigned b, unsigned c,
                                   unsigned& s, unsigned& cy) {
    unsigned ab = a ^ b;
    s = ab ^ c;
    cy = (a & b) | (c & ab);
}

// deterministic per-CTA alpha: warp 0 reduces 56 partials with shfl butterfly
__device__ __forceinline__ void compute_alpha(int n, int tid, float* dst) {
    if (tid < 32) {
        float s = 0.f;
        #pragma unroll
        for (int t = tid; t < H_; t += 32) s += g_partial[n * H_ + t];
        #pragma unroll
        for (int o = 16; o > 0; o >>= 1) s += __shfl_xor_sync(0xffffffffu, s, o);
        if (tid == 0) *dst = fmaxf(2.f * s * (1.f / (float)(C_ * HW_)), 1e-5f);
    }
}

// ---------------- shared memory union ----------------
struct TS { int8_t sm[2][10240]; int srow[32]; float alpha; };          // A 8KB | B 2KB per buf
struct PS { unsigned sw[4608]; unsigned xs[3][58][8]; unsigned char wpc[64][9];
            float m[64]; float alpha; };
union __align__(16) SU { TS t; PS p; };

// ---------------- fused pack kernel: bid<1792 pack_x part, else pack_w part ----------------
__device__ __forceinline__ int8_t sgn8(float v) {
    return (v > 0.f) ? (int8_t)1 : ((v < 0.f) ? (int8_t)-1 : (int8_t)0);
}

__global__ __launch_bounds__(256) void pack_kernel(const float* __restrict__ x,
                                                   const float* __restrict__ wt) {
    __shared__ __align__(4) int8_t tile[C_][60];
    __shared__ float red[256];
    int tid = threadIdx.x;
    int bid = blockIdx.x;

    if (bid < H_ * N_) {
        // ---- pack_x: block (h,n) ----
        int h = bid % H_, n = bid / H_;
        float s = 0.f;
        const float* xb = x + ((size_t)n * C_) * HW_ + (size_t)h * W_;
        #pragma unroll
        for (int it = 0; it < 14; ++it) {
            int idx = it * 256 + tid;           // 0..3583 float4s
            int c = idx / 14, w4 = idx - c * 14;
            float4 v = *(const float4*)(xb + (size_t)c * HW_ + w4 * 4);
            s += fabsf(v.x) + fabsf(v.y) + fabsf(v.z) + fabsf(v.w);
            uchar4 sg;
            sg.x = (unsigned char)sgn8(v.x);
            sg.y = (unsigned char)sgn8(v.y);
            sg.z = (unsigned char)sgn8(v.z);
            sg.w = (unsigned char)sgn8(v.w);
            *(uchar4*)&tile[c][w4 * 4] = sg;
        }
        red[tid] = s;
        __syncthreads();
        #pragma unroll
        for (int off = 128; off > 0; off >>= 1) {
            if (tid < off) red[tid] += red[tid + off];
            __syncthreads();
        }
        if (tid == 0) g_partial[n * H_ + h] = red[0];
        int8_t* dst = g_x8 + (((size_t)n * HP_ + (h + 1)) * HP_ + 1) * C_ + tid;
        int j = tid >> 5, lane = tid & 31;
        #pragma unroll 4
        for (int w = 0; w < W_; ++w) {
            int8_t v = tile[tid][w];
            dst[(size_t)w * C_] = v;
            unsigned bits = __ballot_sync(0xffffffffu, v < 0);
            if (lane == 0) g_xpack[(((size_t)n * H_ + h) * W_ + w) * 8 + j] = bits;
        }
    } else {
        // ---- pack_w: block = output channel o ----
        int o = bid - H_ * N_;
        int c = tid;
        const float* p = wt + ((size_t)o * C_ + c) * 9;
        float s = 0.f;
        int j = c >> 5, lane = c & 31;
        #pragma unroll
        for (int t = 0; t < 9; ++t) {
            float v = p[t];
            s += fabsf(v);
            g_w8[(size_t)o * K_ + t * C_ + c] = sgn8(v);
            unsigned bits = __ballot_sync(0xffffffffu, v < 0.f);
            if (lane == 0) g_wpack[o * 72 + t * 8 + j] = bits;
        }
        red[c] = s;
        __syncthreads();
        #pragma unroll
        for (int off = 128; off > 0; off >>= 1) {
            if (c < off) red[c] += red[c + off];
            __syncthreads();
        }
        if (c == 0) g_m[o] = red[0] * (1.f / (float)K_);
    }
}

// ---------------- tensor path (IMMA implicit GEMM, n < NT_) ----------------
// CTA tile M128 x N32, warp tile m64 x n8. K = 36 chunks of 64.
__device__ __forceinline__ void tensor_path(int tb, float* __restrict__ out, SU& u) {
    int n = tb / (PT_ * 2);
    int rem = tb - n * (PT_ * 2);
    int ptile = rem % PT_, mtile = rem / PT_;
    int tid = threadIdx.x;

    if (tid >= 32 && tid < 64) {
        int p = ptile * 32 + (tid - 32);
        int ph = p / W_, pw = p - ph * W_;
        u.t.srow[tid - 32] = ((n * HP_ + ph) * HP_ + pw) * C_;
    }
    compute_alpha(n, tid, &u.t.alpha);
    __syncthreads();
    uint32_t sbase = smem_u32(u.t.sm);

    int r0 = tid >> 2, uc = tid & 3;          // A rows 0..63 / 64..127
    uint32_t sA0 = r0 * 64 + ((uc ^ ((r0 >> 1) & 3)) << 4);
    int r1 = r0 + 64;
    uint32_t sA1 = r1 * 64 + ((uc ^ ((r1 >> 1) & 3)) << 4);
    int rb = tid >> 2;
    uint32_t sB0 = 8192 + rb * 64 + ((uc ^ ((rb >> 1) & 3)) << 4);
    const int8_t* wbase = g_w8 + (size_t)(mtile * 128) * K_;

    int wid = tid >> 5, L = tid & 31;
    int wm = wid >> 2, wn = wid & 3;
    uint32_t aoff[4], boff;
    #pragma unroll
    for (int mf = 0; mf < 4; ++mf) {
        int row = wm * 64 + mf * 16 + (L & 7) + ((L >> 3) & 1) * 8;
        int uu = L >> 4;
        aoff[mf] = row * 64 + ((uu ^ ((row >> 1) & 3)) << 4);
    }
    {
        int row = wn * 8 + (L & 7);
        int uu = (L >> 3) & 1;
        boff = 8192 + row * 64 + ((uu ^ ((row >> 1) & 3)) << 4);
    }

    int acc[4][4];
    #pragma unroll
    for (int mf = 0; mf < 4; ++mf)
        #pragma unroll
        for (int r = 0; r < 4; ++r) acc[mf][r] = 0;

    auto issue = [&](int ch) {
        int buf = ch & 1;
        int t = ch >> 2, q = ch & 3;
        int kh = t / 3, kw = t - kh * 3;
        int tapoff = (kh * HP_ + kw) * C_ + q * 64;
        const int8_t* wg = wbase + t * 256 + q * 64;
        uint32_t bb = sbase + buf * 10240;
        cp16(bb + sA0, wg + (size_t)r0 * K_ + uc * 16);
        cp16(bb + sA1, wg + (size_t)r1 * K_ + uc * 16);
        if (tid < 128) cp16(bb + sB0, g_x8 + (size_t)u.t.srow[rb] + tapoff + uc * 16);
        asm volatile("cp.async.commit_group;" ::: "memory");
    };

    issue(0);
    for (int ch = 0; ch < 36; ++ch) {
        if (ch + 1 < 36) {
            issue(ch + 1);
            asm volatile("cp.async.wait_group 1;" ::: "memory");
        } else {
            asm volatile("cp.async.wait_group 0;" ::: "memory");
        }
        __syncthreads();
        uint32_t base = sbase + (ch & 1) * 10240;
        #pragma unroll
        for (int s = 0; s < 2; ++s) {
            uint32_t a[4][4], b[2];
            #pragma unroll
            for (int mf = 0; mf < 4; ++mf) ldsm4(a[mf], base + (aoff[mf] ^ (s << 5)));
            ldsm2(b, base + (boff ^ (s << 5)));
            #pragma unroll
            for (int mf = 0; mf < 4; ++mf)
                mma_s8(acc[mf], a[mf], b);
        }
        __syncthreads();
    }

    float av = u.t.alpha;
    int obase = mtile * 128 + wm * 64 + (L >> 2);
    int p = ptile * 32 + wn * 8 + (L & 3) * 2;
    #pragma unroll
    for (int mf = 0; mf < 4; ++mf) {
        int o0 = obase + mf * 16, o1 = o0 + 8;
        float s0 = av * g_m[o0], s1 = av * g_m[o1];
        float* row0 = out + ((size_t)n * O_ + o0) * HW_;
        float* row1 = out + ((size_t)n * O_ + o1) * HW_;
        *(float2*)(row0 + p) = make_float2(s0 * (float)acc[mf][0], s0 * (float)acc[mf][1]);
        *(float2*)(row1 + p) = make_float2(s1 * (float)acc[mf][2], s1 * (float)acc[mf][3]);
    }
}

// ---------------- popcount path (CSA; rows outer, 16 o inner via 8 packed accs) ----------------
__device__ __forceinline__ void popc_path(int pid, float* __restrict__ out, SU& u) {
    int n = NT_ + pid / (H_ * 4);
    int rem = pid - (n - NT_) * (H_ * 4);
    int h = rem >> 2;
    int o0 = (rem & 3) << 6;
    int tid = threadIdx.x;

    compute_alpha(n, tid, &u.p.alpha);
    const unsigned* wg = g_wpack + o0 * 72;
    for (int i = tid; i < 4608; i += 256) u.p.sw[i] = wg[i];
    for (int i = tid; i < 3 * 58 * 8; i += 256) {
        int r = i / 464;
        int rr = i - r * 464;
        int col = rr >> 3, j = rr & 7;
        int hr = h - 1 + r, w = col - 1;
        unsigned v = 0;
        if ((unsigned)hr < 56u && (unsigned)w < 56u)
            v = g_xpack[(((size_t)n * H_ + hr) * W_ + w) * 8 + j];
        u.p.xs[r][col][j] = v;
    }
    if (tid >= 64 && tid < 128) u.p.m[tid - 64] = g_m[o0 + tid - 64];
    __syncthreads();
    for (int i = tid; i < 576; i += 256) {
        int o = i / 9, t = i - o * 9;
        const unsigned* p = &u.p.sw[o * 72 + t * 8];
        int s = 0;
        #pragma unroll
        for (int j = 0; j < 8; ++j) s += __popc(p[j]);
        u.p.wpc[o][t] = (unsigned char)s;
    }
    __syncthreads();

    int w = tid & 63, oy = tid >> 6;
    if (w >= W_) return;

    unsigned rm = 2u | (h > 0 ? 1u : 0u) | (h < H_ - 1 ? 4u : 0u);
    unsigned cm = 2u | (w > 0 ? 1u : 0u) | (w < W_ - 1 ? 4u : 0u);
    unsigned vm = ((rm & 1u) ? cm : 0u) | ((rm & 2u) ? (cm << 3) : 0u) | ((rm & 4u) ? (cm << 6) : 0u);
    int nvalid = __popc(vm);

    // packed accumulators: acc2[p] = acc[2p] | (acc[2p+1] << 16); max 2304 < 2^15
    int acc2[8];
    #pragma unroll
    for (int i = 0; i < 8; ++i) acc2[i] = 0;

    const unsigned* wq = &u.p.sw[oy * 16 * 72];

    #pragma unroll 1
    for (int r = 0; r < 3; ++r) {
        uint4 x0a = *(const uint4*)&u.p.xs[r][w][0];
        uint4 x0b = *(const uint4*)&u.p.xs[r][w][4];
        uint4 x1a = *(const uint4*)&u.p.xs[r][w + 1][0];
        uint4 x1b = *(const uint4*)&u.p.xs[r][w + 1][4];
        uint4 x2a = *(const uint4*)&u.p.xs[r][w + 2][0];
        uint4 x2b = *(const uint4*)&u.p.xs[r][w + 2][4];
        const unsigned* wr = wq + r * 24;
        #pragma unroll
        for (int olp = 0; olp < 8; ++olp) {
            int pc0 = 0, pc1 = 0;
            #pragma unroll
            for (int half = 0; half < 2; ++half) {
                const unsigned* wt = wr + (olp * 2 + half) * 72;
                int pc = 0;
                #pragma unroll
                for (int c = 0; c < 3; ++c) {
                    uint4 a = *(const uint4*)(wt + c * 8);
                    uint4 b = *(const uint4*)(wt + c * 8 + 4);
                    uint4 xa = (c == 0) ? x0a : (c == 1) ? x1a : x2a;
                    uint4 xb = (c == 0) ? x0b : (c == 1) ? x1b : x2b;
                    unsigned e0 = xa.x ^ a.x, e1 = xa.y ^ a.y, e2 = xa.z ^ a.z, e3 = xa.w ^ a.w;
                    unsigned e4 = xb.x ^ b.x, e5 = xb.y ^ b.y, e6 = xb.z ^ b.z, e7 = xb.w ^ b.w;
                    unsigned s1, c1, s2, c2, s3, c3, s4, c4;
                    fa(e0, e1, e2, s1, c1);
                    fa(e3, e4, e5, s2, c2);
                    fa(s1, s2, e6, s3, c3);
                    fa(c1, c2, c3, s4, c4);
                    pc += __popc(s3) + __popc(e7) + 2 * __popc(s4) + 4 * __popc(c4);
                }
                if (half == 0) pc0 = pc; else pc1 = pc;
            }
            acc2[olp] += pc0 + (pc1 << 16);
        }
    }

    // border correction: invalid taps contributed popc(w_t); remove them.
    if (vm != 0x1FFu) {
        #pragma unroll
        for (int t = 0; t < 9; ++t) {
            if (!((vm >> t) & 1u)) {
                #pragma unroll
                for (int olp = 0; olp < 8; ++olp)
                    acc2[olp] -= (int)u.p.wpc[oy * 16 + olp * 2][t]
                               + ((int)u.p.wpc[oy * 16 + olp * 2 + 1][t] << 16);
            }
        }
    }

    float av = u.p.alpha;
    float* orow = out + ((size_t)n * O_ + o0 + oy * 16) * HW_ + h * W_ + w;
    int base = C_ * nvalid;
    #pragma unroll
    for (int olp = 0; olp < 8; ++olp) {
        int a0 = acc2[olp] & 0xFFFF;
        int a1 = (int)((unsigned)acc2[olp] >> 16);
        orow[(size_t)(olp * 2) * HW_]     = av * u.p.m[oy * 16 + olp * 2]     * (float)(base - 2 * a0);
        orow[(size_t)(olp * 2 + 1) * HW_] = av * u.p.m[oy * 16 + olp * 2 + 1] * (float)(base - 2 * a1);
    }
}

// ---------------- fused kernel: groups of 7 CTAs = 2 tensor + 5 popc ----------------
__global__ __launch_bounds__(256, 4) void main_kernel(float* __restrict__ out) {
    __shared__ SU u;
    int bid = blockIdx.x;
    int g = bid / 7, r = bid % 7;
    int tb = g * 2 + r;
    if (r < 2 && tb < TCTA_) {
        tensor_path(tb, out, u);
    } else {
        int nt_before = g * 2 + (r < 2 ? r : 2);
        if (nt_before > TCTA_) nt_before = TCTA_;
        popc_path(bid - nt_before, out, u);
    }
}

// ---------------- launch ----------------
extern "C" void kernel_launch(void* const* d_in, const int* in_sizes, int n_in,
                              void* d_out, int out_size) {
    const float* x  = (const float*)d_in[0];
    const float* wt = (const float*)d_in[1];
    float* out = (float*)d_out;

    pack_kernel<<<H_ * N_ + O_, 256>>>(x, wt);
    main_kernel<<<TCTA_ + PCTA_, 256>>>(out);
}

// round 17
// speedup vs baseline: 1.0891x; 1.0891x over previous
#include <cuda_runtime.h>
#include <cstdint>

// out[n,o,h,w] = alpha[n]*m[o] * sum_{c,kh,kw} sign(x)*sign(w)
// Single fused grid: pack CTAs (first 2048 bids) produce packed signs + flags;
// hybrid conv CTAs spin on per-sample flags then run tensor (n<NT_) or popc path.

#define N_ 32
#define C_ 256
#define H_ 56
#define W_ 56
#define O_ 256
#define HW_ 3136
#define K_ 2304
#define HP_ 58
#define PT_ 98                  // 3136/32 pixel tiles (exact, N32 CTA tile)
#define NT_ 8                   // samples on tensor path
#define TCTA_ (NT_*PT_*2)       // 1568 tensor CTAs
#define PCTA_ ((N_-NT_)*H_*4)   // 5376 popc CTAs
#define STRIDE_ 4
#define PACKX_ (H_*N_)          // 1792
#define PACKCTA_ (PACKX_ + O_)  // 2048

__device__ __align__(16) int8_t   g_x8[(size_t)N_ * HP_ * HP_ * C_];   // NHWC padded s8 signs
__device__ __align__(16) int8_t   g_w8[(size_t)O_ * K_];               // A rows, k=tap*256+c
__device__ __align__(16) unsigned g_xpack[(size_t)N_ * H_ * W_ * 8];   // [n][h][w][j]
__device__ __align__(16) unsigned g_wpack[O_ * 72];                    // [o][t][j]
__device__ float g_partial[N_ * H_];
__device__ float g_m[O_];
__device__ int   g_flags[N_ + 1];   // [n]=x rows done; [N_]=w channels done (memset each launch)

__device__ __forceinline__ uint32_t smem_u32(const void* p) {
    uint32_t a;
    asm("{ .reg .u64 t; cvta.to.shared.u64 t, %1; cvt.u32.u64 %0, t; }" : "=r"(a) : "l"(p));
    return a;
}
__device__ __forceinline__ void cp16(uint32_t saddr, const void* g) {
    asm volatile("cp.async.cg.shared.global [%0], [%1], 16;" :: "r"(saddr), "l"(g));
}
__device__ __forceinline__ void ldsm4(uint32_t* r, uint32_t a) {
    asm volatile("ldmatrix.sync.aligned.m8n8.x4.shared.b16 {%0,%1,%2,%3}, [%4];"
                 : "=r"(r[0]), "=r"(r[1]), "=r"(r[2]), "=r"(r[3]) : "r"(a));
}
__device__ __forceinline__ void ldsm2(uint32_t* r, uint32_t a) {
    asm volatile("ldmatrix.sync.aligned.m8n8.x2.shared.b16 {%0,%1}, [%2];"
                 : "=r"(r[0]), "=r"(r[1]) : "r"(a));
}
__device__ __forceinline__ void mma_s8(int* d, const uint32_t* a, const uint32_t* b) {
    asm volatile("mma.sync.aligned.m16n8k32.row.col.s32.s8.s8.s32 "
                 "{%0,%1,%2,%3}, {%4,%5,%6,%7}, {%8,%9}, {%0,%1,%2,%3};"
                 : "+r"(d[0]), "+r"(d[1]), "+r"(d[2]), "+r"(d[3])
                 : "r"(a[0]), "r"(a[1]), "r"(a[2]), "r"(a[3]), "r"(b[0]), "r"(b[1]));
}
__device__ __forceinline__ void fa(unsigned a, unsigned b, unsigned c,
                                   unsigned& s, unsigned& cy) {
    unsigned ab = a ^ b;
    s = ab ^ c;
    cy = (a & b) | (c & ab);
}

// deterministic per-CTA alpha: warp 0 reduces 56 partials with shfl butterfly
__device__ __forceinline__ void compute_alpha(int n, int tid, float* dst) {
    if (tid < 32) {
        float s = 0.f;
        #pragma unroll
        for (int t = tid; t < H_; t += 32) s += g_partial[n * H_ + t];
        #pragma unroll
        for (int o = 16; o > 0; o >>= 1) s += __shfl_xor_sync(0xffffffffu, s, o);
        if (tid == 0) *dst = fmaxf(2.f * s * (1.f / (float)(C_ * HW_)), 1e-5f);
    }
}

// spin until sample n's pack data + all weights are globally visible
__device__ __forceinline__ void wait_ready(int n, int tid) {
    if (tid == 0) {
        while (((volatile int*)g_flags)[n] < H_) {}
        while (((volatile int*)g_flags)[N_] < O_) {}
    }
    __threadfence();
    __syncthreads();
}

// ---------------- shared memory union ----------------
struct TS { int8_t sm[2][10240]; int srow[32]; float alpha; };          // A 8KB | B 2KB per buf
struct PS { unsigned sw[4608]; unsigned xs[3][58][8]; unsigned char wpc[64][9];
            float m[64]; float alpha; };
struct PK { int8_t tile[C_][60]; float red[256]; };
union __align__(16) SU { TS t; PS p; PK k; };

__device__ __forceinline__ int8_t sgn8(float v) {
    return (v > 0.f) ? (int8_t)1 : ((v < 0.f) ? (int8_t)-1 : (int8_t)0);
}

// ---------------- pack-x part: block (h,n) ----------------
__device__ __forceinline__ void pack_x_part(int bid, const float* __restrict__ x, SU& u) {
    int h = bid % H_, n = bid / H_;
    int tid = threadIdx.x;
    float s = 0.f;
    const float* xb = x + ((size_t)n * C_) * HW_ + (size_t)h * W_;
    #pragma unroll
    for (int it = 0; it < 14; ++it) {
        int idx = it * 256 + tid;               // 0..3583 float4s
        int c = idx / 14, w4 = idx - c * 14;
        float4 v = *(const float4*)(xb + (size_t)c * HW_ + w4 * 4);
        s += fabsf(v.x) + fabsf(v.y) + fabsf(v.z) + fabsf(v.w);
        uchar4 sg;
        sg.x = (unsigned char)sgn8(v.x);
        sg.y = (unsigned char)sgn8(v.y);
        sg.z = (unsigned char)sgn8(v.z);
        sg.w = (unsigned char)sgn8(v.w);
        *(uchar4*)&u.k.tile[c][w4 * 4] = sg;
    }
    u.k.red[tid] = s;
    __syncthreads();
    #pragma unroll
    for (int off = 128; off > 0; off >>= 1) {
        if (tid < off) u.k.red[tid] += u.k.red[tid + off];
        __syncthreads();
    }
    if (tid == 0) g_partial[n * H_ + h] = u.k.red[0];
    int8_t* dst = g_x8 + (((size_t)n * HP_ + (h + 1)) * HP_ + 1) * C_ + tid;
    int j = tid >> 5, lane = tid & 31;
    #pragma unroll 4
    for (int w = 0; w < W_; ++w) {
        int8_t v = u.k.tile[tid][w];
        dst[(size_t)w * C_] = v;
        unsigned bits = __ballot_sync(0xffffffffu, v < 0);
        if (lane == 0) g_xpack[(((size_t)n * H_ + h) * W_ + w) * 8 + j] = bits;
    }
    __threadfence();
    __syncthreads();
    if (tid == 0) atomicAdd(&g_flags[n], 1);
}

// ---------------- pack-w part: block = output channel o ----------------
__device__ __forceinline__ void pack_w_part(int o, const float* __restrict__ wt, SU& u) {
    int c = threadIdx.x;
    const float* p = wt + ((size_t)o * C_ + c) * 9;
    float s = 0.f;
    int j = c >> 5, lane = c & 31;
    #pragma unroll
    for (int t = 0; t < 9; ++t) {
        float v = p[t];
        s += fabsf(v);
        g_w8[(size_t)o * K_ + t * C_ + c] = sgn8(v);
        unsigned bits = __ballot_sync(0xffffffffu, v < 0.f);
        if (lane == 0) g_wpack[o * 72 + t * 8 + j] = bits;
    }
    u.k.red[c] = s;
    __syncthreads();
    #pragma unroll
    for (int off = 128; off > 0; off >>= 1) {
        if (c < off) u.k.red[c] += u.k.red[c + off];
        __syncthreads();
    }
    if (c == 0) g_m[o] = u.k.red[0] * (1.f / (float)K_);
    __threadfence();
    __syncthreads();
    if (c == 0) atomicAdd(&g_flags[N_], 1);
}

// ---------------- tensor path (IMMA implicit GEMM, n < NT_) ----------------
// CTA tile M128 x N32, warp tile m64 x n8. K = 36 chunks of 64.
__device__ __forceinline__ void tensor_path(int tb, float* __restrict__ out, SU& u) {
    int n = tb / (PT_ * 2);
    int rem = tb - n * (PT_ * 2);
    int ptile = rem % PT_, mtile = rem / PT_;
    int tid = threadIdx.x;

    wait_ready(n, tid);
    if (tid >= 32 && tid < 64) {
        int p = ptile * 32 + (tid - 32);
        int ph = p / W_, pw = p - ph * W_;
        u.t.srow[tid - 32] = ((n * HP_ + ph) * HP_ + pw) * C_;
    }
    compute_alpha(n, tid, &u.t.alpha);
    __syncthreads();
    uint32_t sbase = smem_u32(u.t.sm);

    int r0 = tid >> 2, uc = tid & 3;          // A rows 0..63 / 64..127
    uint32_t sA0 = r0 * 64 + ((uc ^ ((r0 >> 1) & 3)) << 4);
    int r1 = r0 + 64;
    uint32_t sA1 = r1 * 64 + ((uc ^ ((r1 >> 1) & 3)) << 4);
    int rb = tid >> 2;
    uint32_t sB0 = 8192 + rb * 64 + ((uc ^ ((rb >> 1) & 3)) << 4);
    const int8_t* wbase = g_w8 + (size_t)(mtile * 128) * K_;

    int wid = tid >> 5, L = tid & 31;
    int wm = wid >> 2, wn = wid & 3;
    uint32_t aoff[4], boff;
    #pragma unroll
    for (int mf = 0; mf < 4; ++mf) {
        int row = wm * 64 + mf * 16 + (L & 7) + ((L >> 3) & 1) * 8;
        int uu = L >> 4;
        aoff[mf] = row * 64 + ((uu ^ ((row >> 1) & 3)) << 4);
    }
    {
        int row = wn * 8 + (L & 7);
        int uu = (L >> 3) & 1;
        boff = 8192 + row * 64 + ((uu ^ ((row >> 1) & 3)) << 4);
    }

    int acc[4][4];
    #pragma unroll
    for (int mf = 0; mf < 4; ++mf)
        #pragma unroll
        for (int r = 0; r < 4; ++r) acc[mf][r] = 0;

    auto issue = [&](int ch) {
        int buf = ch & 1;
        int t = ch >> 2, q = ch & 3;
        int kh = t / 3, kw = t - kh * 3;
        int tapoff = (kh * HP_ + kw) * C_ + q * 64;
        const int8_t* wg = wbase + t * 256 + q * 64;
        uint32_t bb = sbase + buf * 10240;
        cp16(bb + sA0, wg + (size_t)r0 * K_ + uc * 16);
        cp16(bb + sA1, wg + (size_t)r1 * K_ + uc * 16);
        if (tid < 128) cp16(bb + sB0, g_x8 + (size_t)u.t.srow[rb] + tapoff + uc * 16);
        asm volatile("cp.async.commit_group;" ::: "memory");
    };

    issue(0);
    for (int ch = 0; ch < 36; ++ch) {
        if (ch + 1 < 36) {
            issue(ch + 1);
            asm volatile("cp.async.wait_group 1;" ::: "memory");
        } else {
            asm volatile("cp.async.wait_group 0;" ::: "memory");
        }
        __syncthreads();
        uint32_t base = sbase + (ch & 1) * 10240;
        #pragma unroll
        for (int s = 0; s < 2; ++s) {
            uint32_t a[4][4], b[2];
            #pragma unroll
            for (int mf = 0; mf < 4; ++mf) ldsm4(a[mf], base + (aoff[mf] ^ (s << 5)));
            ldsm2(b, base + (boff ^ (s << 5)));
            #pragma unroll
            for (int mf = 0; mf < 4; ++mf)
                mma_s8(acc[mf], a[mf], b);
        }
        __syncthreads();
    }

    float av = u.t.alpha;
    int obase = mtile * 128 + wm * 64 + (L >> 2);
    int p = ptile * 32 + wn * 8 + (L & 3) * 2;
    #pragma unroll
    for (int mf = 0; mf < 4; ++mf) {
        int o0 = obase + mf * 16, o1 = o0 + 8;
        float s0 = av * g_m[o0], s1 = av * g_m[o1];
        float* row0 = out + ((size_t)n * O_ + o0) * HW_;
        float* row1 = out + ((size_t)n * O_ + o1) * HW_;
        *(float2*)(row0 + p) = make_float2(s0 * (float)acc[mf][0], s0 * (float)acc[mf][1]);
        *(float2*)(row1 + p) = make_float2(s1 * (float)acc[mf][2], s1 * (float)acc[mf][3]);
    }
}

// ---------------- popcount path (CSA; rows outer, 16 o inner via 8 packed accs) ----------------
__device__ __forceinline__ void popc_path(int pid, float* __restrict__ out, SU& u) {
    int n = NT_ + pid / (H_ * 4);
    int rem = pid - (n - NT_) * (H_ * 4);
    int h = rem >> 2;
    int o0 = (rem & 3) << 6;
    int tid = threadIdx.x;

    wait_ready(n, tid);
    compute_alpha(n, tid, &u.p.alpha);
    const unsigned* wg = g_wpack + o0 * 72;
    for (int i = tid; i < 4608; i += 256) u.p.sw[i] = wg[i];
    for (int i = tid; i < 3 * 58 * 8; i += 256) {
        int r = i / 464;
        int rr = i - r * 464;
        int col = rr >> 3, j = rr & 7;
        int hr = h - 1 + r, w = col - 1;
        unsigned v = 0;
        if ((unsigned)hr < 56u && (unsigned)w < 56u)
            v = g_xpack[(((size_t)n * H_ + hr) * W_ + w) * 8 + j];
        u.p.xs[r][col][j] = v;
    }
    if (tid >= 64 && tid < 128) u.p.m[tid - 64] = g_m[o0 + tid - 64];
    __syncthreads();
    for (int i = tid; i < 576; i += 256) {
        int o = i / 9, t = i - o * 9;
        const unsigned* p = &u.p.sw[o * 72 + t * 8];
        int s = 0;
        #pragma unroll
        for (int j = 0; j < 8; ++j) s += __popc(p[j]);
        u.p.wpc[o][t] = (unsigned char)s;
    }
    __syncthreads();

    int w = tid & 63, oy = tid >> 6;
    if (w >= W_) return;

    unsigned rm = 2u | (h > 0 ? 1u : 0u) | (h < H_ - 1 ? 4u : 0u);
    unsigned cm = 2u | (w > 0 ? 1u : 0u) | (w < W_ - 1 ? 4u : 0u);
    unsigned vm = ((rm & 1u) ? cm : 0u) | ((rm & 2u) ? (cm << 3) : 0u) | ((rm & 4u) ? (cm << 6) : 0u);
    int nvalid = __popc(vm);

    // packed accumulators: acc2[p] = acc[2p] | (acc[2p+1] << 16); max 2304 < 2^15
    int acc2[8];
    #pragma unroll
    for (int i = 0; i < 8; ++i) acc2[i] = 0;

    const unsigned* wq = &u.p.sw[oy * 16 * 72];

    #pragma unroll 1
    for (int r = 0; r < 3; ++r) {
        uint4 x0a = *(const uint4*)&u.p.xs[r][w][0];
        uint4 x0b = *(const uint4*)&u.p.xs[r][w][4];
        uint4 x1a = *(const uint4*)&u.p.xs[r][w + 1][0];
        uint4 x1b = *(const uint4*)&u.p.xs[r][w + 1][4];
        uint4 x2a = *(const uint4*)&u.p.xs[r][w + 2][0];
        uint4 x2b = *(const uint4*)&u.p.xs[r][w + 2][4];
        const unsigned* wr = wq + r * 24;
        #pragma unroll
        for (int olp = 0; olp < 8; ++olp) {
            int pc0 = 0, pc1 = 0;
            #pragma unroll
            for (int half = 0; half < 2; ++half) {
                const unsigned* wt = wr + (olp * 2 + half) * 72;
                int pc = 0;
                #pragma unroll
                for (int c = 0; c < 3; ++c) {
                    uint4 a = *(const uint4*)(wt + c * 8);
                    uint4 b = *(const uint4*)(wt + c * 8 + 4);
                    uint4 xa = (c == 0) ? x0a : (c == 1) ? x1a : x2a;
                    uint4 xb = (c == 0) ? x0b : (c == 1) ? x1b : x2b;
                    unsigned e0 = xa.x ^ a.x, e1 = xa.y ^ a.y, e2 = xa.z ^ a.z, e3 = xa.w ^ a.w;
                    unsigned e4 = xb.x ^ b.x, e5 = xb.y ^ b.y, e6 = xb.z ^ b.z, e7 = xb.w ^ b.w;
                    unsigned s1, c1, s2, c2, s3, c3, s4, c4;
                    fa(e0, e1, e2, s1, c1);
                    fa(e3, e4, e5, s2, c2);
                    fa(s1, s2, e6, s3, c3);
                    fa(c1, c2, c3, s4, c4);
                    pc += __popc(s3) + __popc(e7) + 2 * __popc(s4) + 4 * __popc(c4);
                }
                if (half == 0) pc0 = pc; else pc1 = pc;
            }
            acc2[olp] += pc0 + (pc1 << 16);
        }
    }

    // border correction: invalid taps contributed popc(w_t); remove them.
    if (vm != 0x1FFu) {
        #pragma unroll
        for (int t = 0; t < 9; ++t) {
            if (!((vm >> t) & 1u)) {
                #pragma unroll
                for (int olp = 0; olp < 8; ++olp)
                    acc2[olp] -= (int)u.p.wpc[oy * 16 + olp * 2][t]
                               + ((int)u.p.wpc[oy * 16 + olp * 2 + 1][t] << 16);
            }
        }
    }

    float av = u.p.alpha;
    float* orow = out + ((size_t)n * O_ + o0 + oy * 16) * HW_ + h * W_ + w;
    int base = C_ * nvalid;
    #pragma unroll
    for (int olp = 0; olp < 8; ++olp) {
        int a0 = acc2[olp] & 0xFFFF;
        int a1 = (int)((unsigned)acc2[olp] >> 16);
        orow[(size_t)(olp * 2) * HW_]     = av * u.p.m[oy * 16 + olp * 2]     * (float)(base - 2 * a0);
        orow[(size_t)(olp * 2 + 1) * HW_] = av * u.p.m[oy * 16 + olp * 2 + 1] * (float)(base - 2 * a1);
    }
}

// ---------------- single fused kernel ----------------
__global__ __launch_bounds__(256, 4) void fused_kernel(const float* __restrict__ x,
                                                       const float* __restrict__ wt,
                                                       float* __restrict__ out) {
    __shared__ SU u;
    int bid = blockIdx.x;
    if (bid < PACKX_) { pack_x_part(bid, x, u); return; }
    if (bid < PACKCTA_) { pack_w_part(bid - PACKX_, wt, u); return; }
    bid -= PACKCTA_;
    bool is_t = (bid % STRIDE_ == 0) && (bid / STRIDE_ < TCTA_);
    if (is_t) {
        tensor_path(bid / STRIDE_, out, u);
    } else {
        int tb = bid / STRIDE_ + 1;
        if (tb > TCTA_) tb = TCTA_;
        popc_path(bid - tb, out, u);
    }
}

// ---------------- launch ----------------
extern "C" void kernel_launch(void* const* d_in, const int* in_sizes, int n_in,
                              void* d_out, int out_size) {
    const float* x  = (const float*)d_in[0];
    const float* wt = (const float*)d_in[1];
    float* out = (float*)d_out;

    void* fp = nullptr;
    cudaGetSymbolAddress(&fp, g_flags);
    cudaMemsetAsync(fp, 0, sizeof(int) * (N_ + 1));

    fused_kernel<<<PACKCTA_ + TCTA_ + PCTA_, 256>>>(x, wt, out);
}